// round 7
// baseline (speedup 1.0000x reference)
#include <cuda_runtime.h>
#include <math.h>
#include <stdint.h>

// SlotAttention GB300 — Round 6: fused attention pass (logits+softmax+partial
// updates in one x̂ sweep) + fully fused slot-update chain (one kernel per
// iteration). Weights pre-transposed for coalesced access. All fp32.

#define Bb 64
#define Nn 4096
#define Dd 256
#define Kk 15
#define Hh 512
#define BN_TOT (Bb * Nn)   // 262144
#define BK_TOT (Bb * Kk)   // 960
#define NCH 16             // n-chunks per batch
#define CHN 256            // n per chunk

// ---------------- scratch ----------------
__device__ float g_xln[(size_t)BN_TOT * Dd];      // 256 MiB
__device__ float g_wqkT[Dd * Dd];                 // [d][e] = (WqᵀWk)[d][e]
__device__ float g_wivT[Dd * 3 * Dd];             // [e][g] = (w_ih·Wv)ᵀ
__device__ float g_whhT[Dd * 3 * Dd];             // [d][j] = w_hh[j][d]
__device__ float g_w1T[Dd * Hh];                  // [d][j] = mlp_w1[j][d]
__device__ float g_w2T[Hh * Dd];                  // [d][j] = mlp_w2[j][d]
__device__ float g_slots[BK_TOT * Dd];
__device__ float g_q[BK_TOT * Dd];
__device__ float g_part[BK_TOT * NCH];
__device__ float g_updpart[(size_t)NCH * BK_TOT * Dd];  // 15.7 MB

// ---------------- helpers ----------------
__device__ __forceinline__ float warp_sum(float v) {
#pragma unroll
    for (int o = 16; o > 0; o >>= 1) v += __shfl_xor_sync(0xffffffffu, v, o);
    return v;
}
__device__ __forceinline__ float sigmoidf_(float x) { return 1.0f / (1.0f + expf(-x)); }

// dot of smem rows S[8][srow] against transposed weight column j:
// acc[r] += sum_d S[r][d] * WT[d*J + j]
template <int K4>
__device__ __forceinline__ void dotT(float acc[8], const float* S, int srow,
                                     const float* __restrict__ WT, int J, int j) {
#pragma unroll 2
    for (int d4 = 0; d4 < K4; d4++) {
        float w0 = WT[(4 * d4 + 0) * J + j];
        float w1 = WT[(4 * d4 + 1) * J + j];
        float w2 = WT[(4 * d4 + 2) * J + j];
        float w3 = WT[(4 * d4 + 3) * J + j];
#pragma unroll
        for (int r = 0; r < 8; r++) {
            const float4 sv = *(const float4*)(S + r * srow + d4 * 4);
            acc[r] += sv.x * w0 + sv.y * w1 + sv.z * w2 + sv.w * w3;
        }
    }
}

// warp-cooperative LayerNorm of one 256-row (one warp per row)
__device__ __forceinline__ void warp_ln_row(const float* src, float* dst,
                                            const float* __restrict__ w,
                                            const float* __restrict__ b, int lane) {
    float vals[8];
    float s = 0.f, s2 = 0.f;
#pragma unroll
    for (int k = 0; k < 8; k++) {
        float v = src[lane + 32 * k];
        vals[k] = v; s += v; s2 += v * v;
    }
    s = warp_sum(s); s2 = warp_sum(s2);
    float m = s * (1.0f / 256.0f);
    float rs = rsqrtf(s2 * (1.0f / 256.0f) - m * m + 1e-5f);
#pragma unroll
    for (int k = 0; k < 8; k++) {
        int d = lane + 32 * k;
        dst[d] = (vals[k] - m) * rs * w[d] + b[d];
    }
}

// ---------------- big LN over inputs ----------------
__global__ void ln_apply_kernel(const float* __restrict__ x, float* __restrict__ y,
                                const float* __restrict__ w, const float* __restrict__ bb) {
    int row = blockIdx.x * 8 + threadIdx.y;
    int lane = threadIdx.x;
    const float* xr = x + (size_t)row * Dd;
    float v[8];
    float s = 0.f, s2 = 0.f;
#pragma unroll
    for (int j = 0; j < 8; j++) {
        v[j] = xr[j * 32 + lane];
        s += v[j]; s2 += v[j] * v[j];
    }
    s = warp_sum(s); s2 = warp_sum(s2);
    float m = s * (1.0f / 256.0f);
    float rs = rsqrtf(s2 * (1.0f / 256.0f) - m * m + 1e-5f);
    float* yr = y + (size_t)row * Dd;
#pragma unroll
    for (int j = 0; j < 8; j++) {
        int dd = j * 32 + lane;
        yr[dd] = (v[j] - m) * rs * w[dd] + bb[dd];
    }
}

// ---------------- precompute: wqkT[a][b] = Σ_j Wq[j][a]·Wk[j][b] ----------------
__global__ __launch_bounds__(256) void atb_kernel(const float* __restrict__ X,
                                                  const float* __restrict__ Y,
                                                  float* __restrict__ C) {
    __shared__ float Xs[16][68];
    __shared__ float Ys[16][68];
    int e0 = blockIdx.x * 64, d0 = blockIdx.y * 64;
    int tid = threadIdx.x;
    int row_t = tid >> 4, col_t = tid & 15;
    int jr = tid >> 4, c4 = (tid & 15) << 2;
    float acc[4][4];
#pragma unroll
    for (int i = 0; i < 4; i++)
#pragma unroll
        for (int j = 0; j < 4; j++) acc[i][j] = 0.f;
    for (int jb = 0; jb < 256; jb += 16) {
        float4 xv = *(const float4*)(X + (size_t)(jb + jr) * Dd + e0 + c4);
        Xs[jr][c4 + 0] = xv.x; Xs[jr][c4 + 1] = xv.y;
        Xs[jr][c4 + 2] = xv.z; Xs[jr][c4 + 3] = xv.w;
        float4 yv = *(const float4*)(Y + (size_t)(jb + jr) * Dd + d0 + c4);
        Ys[jr][c4 + 0] = yv.x; Ys[jr][c4 + 1] = yv.y;
        Ys[jr][c4 + 2] = yv.z; Ys[jr][c4 + 3] = yv.w;
        __syncthreads();
#pragma unroll
        for (int k = 0; k < 16; k++)
#pragma unroll
            for (int i = 0; i < 4; i++)
#pragma unroll
                for (int j = 0; j < 4; j++)
                    acc[i][j] += Xs[k][row_t * 4 + i] * Ys[k][col_t * 4 + j];
        __syncthreads();
    }
#pragma unroll
    for (int i = 0; i < 4; i++)
#pragma unroll
        for (int j = 0; j < 4; j++)
            C[(size_t)(e0 + row_t * 4 + i) * Dd + d0 + col_t * 4 + j] = acc[i][j];
}

// ---------------- precompute: wivT[e][g] = Σ_d w_ih[g,d]·Wv[d,e] ----------------
__global__ __launch_bounds__(256) void ab_t_kernel(const float* __restrict__ A,
                                                   const float* __restrict__ B,
                                                   float* __restrict__ CT) {
    __shared__ float As[16][68];
    __shared__ float Bs[16][68];
    int g0 = blockIdx.x * 64, e0 = blockIdx.y * 64;
    int tid = threadIdx.x;
    int row_t = tid >> 4, col_t = tid & 15;
    int r = tid >> 2, k4 = (tid & 3) << 2;
    int jr = tid >> 4, c4 = (tid & 15) << 2;
    float acc[4][4];
#pragma unroll
    for (int i = 0; i < 4; i++)
#pragma unroll
        for (int j = 0; j < 4; j++) acc[i][j] = 0.f;
    for (int db = 0; db < 256; db += 16) {
        float4 av = *(const float4*)(A + (size_t)(g0 + r) * Dd + db + k4);
        As[k4 + 0][r] = av.x; As[k4 + 1][r] = av.y;
        As[k4 + 2][r] = av.z; As[k4 + 3][r] = av.w;
        float4 bv = *(const float4*)(B + (size_t)(db + jr) * Dd + e0 + c4);
        Bs[jr][c4 + 0] = bv.x; Bs[jr][c4 + 1] = bv.y;
        Bs[jr][c4 + 2] = bv.z; Bs[jr][c4 + 3] = bv.w;
        __syncthreads();
#pragma unroll
        for (int k = 0; k < 16; k++)
#pragma unroll
            for (int i = 0; i < 4; i++)
#pragma unroll
                for (int j = 0; j < 4; j++)
                    acc[i][j] += As[k][row_t * 4 + i] * Bs[k][col_t * 4 + j];
        __syncthreads();
    }
#pragma unroll
    for (int i = 0; i < 4; i++)
#pragma unroll
        for (int j = 0; j < 4; j++)
            CT[(size_t)(e0 + col_t * 4 + j) * 768 + g0 + row_t * 4 + i] = acc[i][j];
}

// ---------------- generic transpose: out[c][r] = in[r][c] ----------------
__global__ void transpose_kernel(const float* __restrict__ in, float* __restrict__ out,
                                 int R, int C) {
    __shared__ float tile[32][33];
    int c0 = blockIdx.x * 32, r0 = blockIdx.y * 32;
    int x = threadIdx.x, y = threadIdx.y;
#pragma unroll
    for (int k = 0; k < 32; k += 8)
        if (r0 + y + k < R && c0 + x < C)
            tile[y + k][x] = in[(size_t)(r0 + y + k) * C + c0 + x];
    __syncthreads();
#pragma unroll
    for (int k = 0; k < 32; k += 8)
        if (c0 + y + k < C && r0 + x < R)
            out[(size_t)(c0 + y + k) * R + r0 + x] = tile[x][y + k];
}

// ---------------- slots init ----------------
__global__ void slots_init_kernel(const float* __restrict__ mu,
                                  const float* __restrict__ ls,
                                  const float* __restrict__ noise) {
    int i = blockIdx.x * 256 + threadIdx.x;
    int kd = i % (Kk * Dd);
    g_slots[i] = mu[kd] + expf(ls[kd]) * noise[i];
}

// ---------------- ln_slots + q (init before first iteration) ----------------
__global__ __launch_bounds__(256) void slot_lnq_kernel(const float* __restrict__ lns_w,
                                                       const float* __restrict__ lns_b) {
    __shared__ float a_s[8][256];
    int t = threadIdx.x, lane = t & 31, wid = t >> 5;
    int row0 = blockIdx.x * 8;
    warp_ln_row(g_slots + (size_t)(row0 + wid) * Dd, &a_s[wid][0], lns_w, lns_b, lane);
    __syncthreads();
    float qa[8] = {0, 0, 0, 0, 0, 0, 0, 0};
    dotT<64>(qa, &a_s[0][0], 256, g_wqkT, 256, t);
#pragma unroll
    for (int r = 0; r < 8; r++) g_q[(size_t)(row0 + r) * Dd + t] = qa[r];
}

// ---------------- fused attention pass ----------------
// grid (NCH, Bb), block 256. Phase 1: logits+softmax for 256 n's.
// Phase 2 (non-final): accumulate unnormalized U partials + rowsum partials.
// Final: write attn to attn_out, skip phase 2.
__global__ __launch_bounds__(256) void attn_pass_kernel(const float* __restrict__ q,
                                                        const float* __restrict__ xln,
                                                        float* __restrict__ attn_out,
                                                        int final_pass) {
    __shared__ float qs[Kk * Dd];
    __shared__ float as[Kk][CHN];
    __shared__ float red2[Kk][8];
    int b = blockIdx.y, chunk = blockIdx.x, t = threadIdx.x;
    int lane = t & 31, wid = t >> 5;

    const float4* qb = (const float4*)(q + (size_t)b * Kk * Dd);
    float4* qs4 = (float4*)qs;
    for (int i = t; i < Kk * 64; i += 256) qs4[i] = qb[i];
    __syncthreads();

    size_t nbase = (size_t)b * Nn + chunk * CHN;
    const float4* xr = (const float4*)(xln + (nbase + t) * Dd);
    float l[Kk];
#pragma unroll
    for (int s = 0; s < Kk; s++) l[s] = 0.f;
#pragma unroll 4
    for (int d4 = 0; d4 < 64; d4++) {
        float4 kv = xr[d4];
#pragma unroll
        for (int s = 0; s < Kk; s++) {
            float4 qv = qs4[s * 64 + d4];
            l[s] += qv.x * kv.x + qv.y * kv.y + qv.z * kv.z + qv.w * kv.w;
        }
    }
    float mx = -1e30f;
#pragma unroll
    for (int s = 0; s < Kk; s++) { l[s] *= 0.0625f; mx = fmaxf(mx, l[s]); }
    float sum = 0.f;
#pragma unroll
    for (int s = 0; s < Kk; s++) { l[s] = expf(l[s] - mx); sum += l[s]; }
    float inv = 1.0f / sum;

    if (final_pass) {
#pragma unroll
        for (int s = 0; s < Kk; s++)
            attn_out[((size_t)(b * Kk + s)) * Nn + chunk * CHN + t] = l[s] * inv;
        return;
    }

#pragma unroll
    for (int s = 0; s < Kk; s++) {
        l[s] *= inv;
        as[s][t] = l[s];
    }
    // partial rowsums (over this chunk's n)
#pragma unroll
    for (int s = 0; s < Kk; s++) {
        float w = warp_sum(l[s]);
        if (lane == 0) red2[s][wid] = w;
    }
    __syncthreads();
    if (t < Kk) {
        float s8 = 0.f;
#pragma unroll
        for (int w = 0; w < 8; w++) s8 += red2[t][w];
        g_part[(b * Kk + t) * NCH + chunk] = s8;
    }
    // phase 2: U_partial[s][d=t] = Σ_n as[s][n] * x̂[n][d]
    float acc[Kk];
#pragma unroll
    for (int s = 0; s < Kk; s++) acc[s] = 0.f;
    const float* xp = xln + nbase * Dd + t;
#pragma unroll 2
    for (int n4 = 0; n4 < 64; n4++) {
        float x0 = xp[(4 * n4 + 0) * Dd];
        float x1 = xp[(4 * n4 + 1) * Dd];
        float x2 = xp[(4 * n4 + 2) * Dd];
        float x3 = xp[(4 * n4 + 3) * Dd];
#pragma unroll
        for (int s = 0; s < Kk; s++) {
            float4 a4 = *(const float4*)&as[s][4 * n4];
            acc[s] += a4.x * x0 + a4.y * x1 + a4.z * x2 + a4.w * x3;
        }
    }
#pragma unroll
    for (int s = 0; s < Kk; s++)
        g_updpart[((size_t)chunk * BK_TOT + b * Kk + s) * Dd + t] = acc[s];
}

// ---------------- fused slot update: U-reduce → GRU → MLP → LN → q ----------------
// grid 120, block 256, 8 slot-rows per block.
__global__ __launch_bounds__(256) void slot_update_kernel(
    const float* __restrict__ bih, const float* __restrict__ bhh,
    const float* __restrict__ b1, const float* __restrict__ b2,
    const float* __restrict__ lnm_w, const float* __restrict__ lnm_b,
    const float* __restrict__ lns_w, const float* __restrict__ lns_b) {
    __shared__ float u_s[8][256];
    __shared__ float h_s[8][256];
    __shared__ float a_s[8][256];
    __shared__ float h1_s[8][512];
    __shared__ float inv_s[8];
    int t = threadIdx.x, lane = t & 31, wid = t >> 5;
    int row0 = blockIdx.x * 8;

#pragma unroll
    for (int r = 0; r < 8; r++) h_s[r][t] = g_slots[(size_t)(row0 + r) * Dd + t];
    if (t < 8) {
        float s = 0.f;
#pragma unroll
        for (int c = 0; c < NCH; c++) s += g_part[(row0 + t) * NCH + c];
        inv_s[t] = 1.0f / (s + 1e-8f);
    }
    __syncthreads();
#pragma unroll
    for (int r = 0; r < 8; r++) {
        float a = 0.f;
#pragma unroll
        for (int c = 0; c < NCH; c++)
            a += g_updpart[((size_t)c * BK_TOT + row0 + r) * Dd + t];
        u_s[r][t] = a * inv_s[r];
    }
    __syncthreads();

    // GRU gates (j = t, 256+t, 512+t of the 768-wide gate vectors)
    float ri[8] = {0}, rh[8] = {0}, zi[8] = {0}, zh[8] = {0}, ni[8] = {0}, nh[8] = {0};
    dotT<64>(ri, &u_s[0][0], 256, g_wivT, 768, t);
    dotT<64>(rh, &h_s[0][0], 256, g_whhT, 768, t);
    dotT<64>(zi, &u_s[0][0], 256, g_wivT, 768, 256 + t);
    dotT<64>(zh, &h_s[0][0], 256, g_whhT, 768, 256 + t);
    dotT<64>(ni, &u_s[0][0], 256, g_wivT, 768, 512 + t);
    dotT<64>(nh, &h_s[0][0], 256, g_whhT, 768, 512 + t);
    float bir = bih[t], bhr = bhh[t];
    float biz = bih[256 + t], bhz = bhh[256 + t];
    float bin = bih[512 + t], bhn = bhh[512 + t];
    __syncthreads();
#pragma unroll
    for (int r = 0; r < 8; r++) {
        float rg = sigmoidf_(ri[r] + bir + rh[r] + bhr);
        float zg = sigmoidf_(zi[r] + biz + zh[r] + bhz);
        float ng = tanhf(ni[r] + bin + rg * (nh[r] + bhn));
        h_s[r][t] = (1.0f - zg) * ng + zg * h_s[r][t];
    }
    __syncthreads();
    // ln_mlp
    warp_ln_row(&h_s[wid][0], &a_s[wid][0], lnm_w, lnm_b, lane);
    __syncthreads();
    // mlp1 (relu)
    float m0[8] = {0}, m1[8] = {0};
    dotT<64>(m0, &a_s[0][0], 256, g_w1T, 512, t);
    dotT<64>(m1, &a_s[0][0], 256, g_w1T, 512, 256 + t);
    float b1a = b1[t], b1b = b1[256 + t];
#pragma unroll
    for (int r = 0; r < 8; r++) {
        h1_s[r][t] = fmaxf(m0[r] + b1a, 0.f);
        h1_s[r][256 + t] = fmaxf(m1[r] + b1b, 0.f);
    }
    __syncthreads();
    // mlp2 + residual
    float m2[8] = {0};
    dotT<128>(m2, &h1_s[0][0], 512, g_w2T, 256, t);
    float b2t = b2[t];
#pragma unroll
    for (int r = 0; r < 8; r++) {
        float ns = h_s[r][t] + m2[r] + b2t;
        g_slots[(size_t)(row0 + r) * Dd + t] = ns;
        a_s[r][t] = ns;
    }
    __syncthreads();
    // ln_slots → u_s, then q for next iteration / final attention
    warp_ln_row(&a_s[wid][0], &u_s[wid][0], lns_w, lns_b, lane);
    __syncthreads();
    float qa[8] = {0};
    dotT<64>(qa, &u_s[0][0], 256, g_wqkT, 256, t);
#pragma unroll
    for (int r = 0; r < 8; r++) g_q[(size_t)(row0 + r) * Dd + t] = qa[r];
}

__global__ void copy_kernel(const float* __restrict__ src, float* __restrict__ dst, int n) {
    int i = blockIdx.x * 256 + threadIdx.x;
    if (i < n) dst[i] = src[i];
}

// ---------------- host orchestration ----------------
extern "C" void kernel_launch(void* const* d_in, const int* in_sizes, int n_in,
                              void* d_out, int out_size) {
    const float* inputs        = (const float*)d_in[0];
    const float* slot_noise    = (const float*)d_in[1];
    const float* slots_mu      = (const float*)d_in[2];
    const float* slots_logsig  = (const float*)d_in[3];
    const float* Wq            = (const float*)d_in[4];
    const float* Wk            = (const float*)d_in[5];
    const float* Wv            = (const float*)d_in[6];
    const float* w_ih          = (const float*)d_in[7];
    const float* w_hh          = (const float*)d_in[8];
    const float* b_ih          = (const float*)d_in[9];
    const float* b_hh          = (const float*)d_in[10];
    const float* mlp_w1        = (const float*)d_in[11];
    const float* mlp_b1        = (const float*)d_in[12];
    const float* mlp_w2        = (const float*)d_in[13];
    const float* mlp_b2        = (const float*)d_in[14];
    const float* ln_in_w       = (const float*)d_in[15];
    const float* ln_in_b       = (const float*)d_in[16];
    const float* ln_s_w        = (const float*)d_in[17];
    const float* ln_s_b        = (const float*)d_in[18];
    const float* ln_m_w        = (const float*)d_in[19];
    const float* ln_m_b        = (const float*)d_in[20];
    float* out = (float*)d_out;

    float *p_xln, *p_wqkT, *p_wivT, *p_whhT, *p_w1T, *p_w2T, *p_q, *p_slots;
    cudaGetSymbolAddress((void**)&p_xln, g_xln);
    cudaGetSymbolAddress((void**)&p_wqkT, g_wqkT);
    cudaGetSymbolAddress((void**)&p_wivT, g_wivT);
    cudaGetSymbolAddress((void**)&p_whhT, g_whhT);
    cudaGetSymbolAddress((void**)&p_w1T, g_w1T);
    cudaGetSymbolAddress((void**)&p_w2T, g_w2T);
    cudaGetSymbolAddress((void**)&p_q, g_q);
    cudaGetSymbolAddress((void**)&p_slots, g_slots);

    // setup: x̂, folded/transposed weights, slots, initial q
    ln_apply_kernel<<<BN_TOT / 8, dim3(32, 8)>>>(inputs, p_xln, ln_in_w, ln_in_b);
    atb_kernel<<<dim3(4, 4), 256>>>(Wq, Wk, p_wqkT);         // wqkT[d][e]
    ab_t_kernel<<<dim3(12, 4), 256>>>(w_ih, Wv, p_wivT);     // wivT[e][g]
    transpose_kernel<<<dim3(8, 24), dim3(32, 8)>>>(w_hh, p_whhT, 768, 256);
    transpose_kernel<<<dim3(8, 16), dim3(32, 8)>>>(mlp_w1, p_w1T, 512, 256);
    transpose_kernel<<<dim3(16, 8), dim3(32, 8)>>>(mlp_w2, p_w2T, 256, 512);
    slots_init_kernel<<<BK_TOT, 256>>>(slots_mu, slots_logsig, slot_noise);
    slot_lnq_kernel<<<120, 256>>>(ln_s_w, ln_s_b);

    for (int it = 0; it < 3; it++) {
        attn_pass_kernel<<<dim3(NCH, Bb), 256>>>(p_q, p_xln, nullptr, 0);
        slot_update_kernel<<<120, 256>>>(b_ih, b_hh, mlp_b1, mlp_b2,
                                         ln_m_w, ln_m_b, ln_s_w, ln_s_b);
    }

    // final attention (softmax only) + slots output
    attn_pass_kernel<<<dim3(NCH, Bb), 256>>>(p_q, p_xln, out + BK_TOT * Dd, 1);
    copy_kernel<<<960, 256>>>(p_slots, out, BK_TOT * Dd);
}

// round 8
// speedup vs baseline: 1.2551x; 1.2551x over previous
#include <cuda_runtime.h>
#include <math.h>
#include <stdint.h>

// SlotAttention GB300 — Round 7: fused attn pass (logits+softmax+U-partials in
// one x̂ sweep) + fused slot chain with float4 weight-row streaming (weights in
// natural [out][in] layout; thread t owns output column t). All fp32.

#define Bb 64
#define Nn 4096
#define Dd 256
#define Kk 15
#define Hh 512
#define BN_TOT (Bb * Nn)   // 262144
#define BK_TOT (Bb * Kk)   // 960
#define NCH 16             // n-chunks per batch
#define CHN 256            // n per chunk

// ---------------- scratch ----------------
__device__ float g_xln[(size_t)BN_TOT * Dd];      // 256 MiB
__device__ float g_wqk[Dd * Dd];                  // [e][d] = Σ_j Wk[j,e]·Wq[j,d]
__device__ float g_wiv[3 * Dd * Dd];              // [g][e] = Σ_d w_ih[g,d]·Wv[d,e]
__device__ float g_slots[BK_TOT * Dd];
__device__ float g_q[BK_TOT * Dd];
__device__ float g_part[BK_TOT * NCH];
__device__ float g_updpart[(size_t)NCH * BK_TOT * Dd];  // 15.7 MB

// ---------------- helpers ----------------
__device__ __forceinline__ float warp_sum(float v) {
#pragma unroll
    for (int o = 16; o > 0; o >>= 1) v += __shfl_xor_sync(0xffffffffu, v, o);
    return v;
}
__device__ __forceinline__ float sigmoidf_(float x) { return 1.0f / (1.0f + expf(-x)); }

// acc[r] += dot(S[r][0..4*K4), Wrow[0..4*K4))  — Wrow loaded as float4 per thread,
// S rows read as warp-uniform broadcasts from smem.
template <int K4>
__device__ __forceinline__ void dot4(float acc[8], const float* S, int srow,
                                     const float* __restrict__ Wrow) {
    const float4* w4 = (const float4*)Wrow;
#pragma unroll 4
    for (int d4 = 0; d4 < K4; d4++) {
        float4 w = w4[d4];
#pragma unroll
        for (int r = 0; r < 8; r++) {
            const float4 sv = *(const float4*)(S + r * srow + d4 * 4);
            acc[r] += sv.x * w.x + sv.y * w.y + sv.z * w.z + sv.w * w.w;
        }
    }
}

// warp-cooperative LayerNorm of one 256-row (one warp per row)
__device__ __forceinline__ void warp_ln_row(const float* src, float* dst,
                                            const float* __restrict__ w,
                                            const float* __restrict__ b, int lane) {
    float vals[8];
    float s = 0.f, s2 = 0.f;
#pragma unroll
    for (int k = 0; k < 8; k++) {
        float v = src[lane + 32 * k];
        vals[k] = v; s += v; s2 += v * v;
    }
    s = warp_sum(s); s2 = warp_sum(s2);
    float m = s * (1.0f / 256.0f);
    float rs = rsqrtf(s2 * (1.0f / 256.0f) - m * m + 1e-5f);
#pragma unroll
    for (int k = 0; k < 8; k++) {
        int d = lane + 32 * k;
        dst[d] = (vals[k] - m) * rs * w[d] + b[d];
    }
}

// ---------------- big LN over inputs ----------------
__global__ void ln_apply_kernel(const float* __restrict__ x, float* __restrict__ y,
                                const float* __restrict__ w, const float* __restrict__ bb) {
    int row = blockIdx.x * 8 + threadIdx.y;
    int lane = threadIdx.x;
    const float* xr = x + (size_t)row * Dd;
    float v[8];
    float s = 0.f, s2 = 0.f;
#pragma unroll
    for (int j = 0; j < 8; j++) {
        v[j] = xr[j * 32 + lane];
        s += v[j]; s2 += v[j] * v[j];
    }
    s = warp_sum(s); s2 = warp_sum(s2);
    float m = s * (1.0f / 256.0f);
    float rs = rsqrtf(s2 * (1.0f / 256.0f) - m * m + 1e-5f);
    float* yr = y + (size_t)row * Dd;
#pragma unroll
    for (int j = 0; j < 8; j++) {
        int dd = j * 32 + lane;
        yr[dd] = (v[j] - m) * rs * w[dd] + bb[dd];
    }
}

// ---------------- precompute: C[e][d] = Σ_j X[j][e]·Y[j][d]  (XᵀY) ----------------
__global__ __launch_bounds__(256) void atb_kernel(const float* __restrict__ X,
                                                  const float* __restrict__ Y,
                                                  float* __restrict__ C) {
    __shared__ float Xs[16][68];
    __shared__ float Ys[16][68];
    int e0 = blockIdx.x * 64, d0 = blockIdx.y * 64;
    int tid = threadIdx.x;
    int row_t = tid >> 4, col_t = tid & 15;
    int jr = tid >> 4, c4 = (tid & 15) << 2;
    float acc[4][4];
#pragma unroll
    for (int i = 0; i < 4; i++)
#pragma unroll
        for (int j = 0; j < 4; j++) acc[i][j] = 0.f;
    for (int jb = 0; jb < 256; jb += 16) {
        float4 xv = *(const float4*)(X + (size_t)(jb + jr) * Dd + e0 + c4);
        Xs[jr][c4 + 0] = xv.x; Xs[jr][c4 + 1] = xv.y;
        Xs[jr][c4 + 2] = xv.z; Xs[jr][c4 + 3] = xv.w;
        float4 yv = *(const float4*)(Y + (size_t)(jb + jr) * Dd + d0 + c4);
        Ys[jr][c4 + 0] = yv.x; Ys[jr][c4 + 1] = yv.y;
        Ys[jr][c4 + 2] = yv.z; Ys[jr][c4 + 3] = yv.w;
        __syncthreads();
#pragma unroll
        for (int k = 0; k < 16; k++)
#pragma unroll
            for (int i = 0; i < 4; i++)
#pragma unroll
                for (int j = 0; j < 4; j++)
                    acc[i][j] += Xs[k][row_t * 4 + i] * Ys[k][col_t * 4 + j];
        __syncthreads();
    }
#pragma unroll
    for (int i = 0; i < 4; i++)
#pragma unroll
        for (int j = 0; j < 4; j++)
            C[(size_t)(e0 + row_t * 4 + i) * Dd + d0 + col_t * 4 + j] = acc[i][j];
}

// ---------------- precompute: C[g][e] = Σ_d A[g][d]·B[d][e]  (A·B) ----------------
__global__ __launch_bounds__(256) void ab_kernel(const float* __restrict__ A,
                                                 const float* __restrict__ B,
                                                 float* __restrict__ C) {
    __shared__ float As[16][68];
    __shared__ float Bs[16][68];
    int g0 = blockIdx.x * 64, e0 = blockIdx.y * 64;
    int tid = threadIdx.x;
    int row_t = tid >> 4, col_t = tid & 15;
    int r = tid >> 2, k4 = (tid & 3) << 2;
    int jr = tid >> 4, c4 = (tid & 15) << 2;
    float acc[4][4];
#pragma unroll
    for (int i = 0; i < 4; i++)
#pragma unroll
        for (int j = 0; j < 4; j++) acc[i][j] = 0.f;
    for (int db = 0; db < 256; db += 16) {
        float4 av = *(const float4*)(A + (size_t)(g0 + r) * Dd + db + k4);
        As[k4 + 0][r] = av.x; As[k4 + 1][r] = av.y;
        As[k4 + 2][r] = av.z; As[k4 + 3][r] = av.w;
        float4 bv = *(const float4*)(B + (size_t)(db + jr) * Dd + e0 + c4);
        Bs[jr][c4 + 0] = bv.x; Bs[jr][c4 + 1] = bv.y;
        Bs[jr][c4 + 2] = bv.z; Bs[jr][c4 + 3] = bv.w;
        __syncthreads();
#pragma unroll
        for (int k = 0; k < 16; k++)
#pragma unroll
            for (int i = 0; i < 4; i++)
#pragma unroll
                for (int j = 0; j < 4; j++)
                    acc[i][j] += As[k][row_t * 4 + i] * Bs[k][col_t * 4 + j];
        __syncthreads();
    }
#pragma unroll
    for (int i = 0; i < 4; i++)
#pragma unroll
        for (int j = 0; j < 4; j++)
            C[(size_t)(g0 + row_t * 4 + i) * Dd + e0 + col_t * 4 + j] = acc[i][j];
}

// ---------------- slots init ----------------
__global__ void slots_init_kernel(const float* __restrict__ mu,
                                  const float* __restrict__ ls,
                                  const float* __restrict__ noise) {
    int i = blockIdx.x * 256 + threadIdx.x;
    int kd = i % (Kk * Dd);
    g_slots[i] = mu[kd] + expf(ls[kd]) * noise[i];
}

// ---------------- ln_slots + q (before first iteration) ----------------
__global__ __launch_bounds__(256) void slot_lnq_kernel(const float* __restrict__ lns_w,
                                                       const float* __restrict__ lns_b) {
    __shared__ float a_s[8][256];
    int t = threadIdx.x, lane = t & 31, wid = t >> 5;
    int row0 = blockIdx.x * 8;
    warp_ln_row(g_slots + (size_t)(row0 + wid) * Dd, &a_s[wid][0], lns_w, lns_b, lane);
    __syncthreads();
    float qa[8] = {0, 0, 0, 0, 0, 0, 0, 0};
    dot4<64>(qa, &a_s[0][0], 256, g_wqk + (size_t)t * Dd);
#pragma unroll
    for (int r = 0; r < 8; r++) g_q[(size_t)(row0 + r) * Dd + t] = qa[r];
}

// ---------------- fused attention pass ----------------
// grid (NCH, Bb), block 256. Phase 1: logits+softmax over slots for 256 n's.
// Non-final: accumulate unnormalized U partials + rowsum partials (phase 2).
// Final: write attn to attn_out, skip phase 2.
__global__ __launch_bounds__(256) void attn_pass_kernel(const float* __restrict__ q,
                                                        const float* __restrict__ xln,
                                                        float* __restrict__ attn_out,
                                                        int final_pass) {
    __shared__ float qs[Kk * Dd];
    __shared__ float as[Kk][CHN];
    __shared__ float red2[Kk][8];
    int b = blockIdx.y, chunk = blockIdx.x, t = threadIdx.x;
    int lane = t & 31, wid = t >> 5;

    const float4* qb = (const float4*)(q + (size_t)b * Kk * Dd);
    float4* qs4 = (float4*)qs;
    for (int i = t; i < Kk * 64; i += 256) qs4[i] = qb[i];
    __syncthreads();

    size_t nbase = (size_t)b * Nn + chunk * CHN;
    const float4* xr = (const float4*)(xln + (nbase + t) * Dd);
    float l[Kk];
#pragma unroll
    for (int s = 0; s < Kk; s++) l[s] = 0.f;
#pragma unroll 4
    for (int d4 = 0; d4 < 64; d4++) {
        float4 kv = xr[d4];
#pragma unroll
        for (int s = 0; s < Kk; s++) {
            float4 qv = qs4[s * 64 + d4];
            l[s] += qv.x * kv.x + qv.y * kv.y + qv.z * kv.z + qv.w * kv.w;
        }
    }
    float mx = -1e30f;
#pragma unroll
    for (int s = 0; s < Kk; s++) { l[s] *= 0.0625f; mx = fmaxf(mx, l[s]); }
    float sum = 0.f;
#pragma unroll
    for (int s = 0; s < Kk; s++) { l[s] = expf(l[s] - mx); sum += l[s]; }
    float inv = 1.0f / sum;

    if (final_pass) {
#pragma unroll
        for (int s = 0; s < Kk; s++)
            attn_out[((size_t)(b * Kk + s)) * Nn + chunk * CHN + t] = l[s] * inv;
        return;
    }

#pragma unroll
    for (int s = 0; s < Kk; s++) {
        l[s] *= inv;
        as[s][t] = l[s];
    }
#pragma unroll
    for (int s = 0; s < Kk; s++) {
        float w = warp_sum(l[s]);
        if (lane == 0) red2[s][wid] = w;
    }
    __syncthreads();
    if (t < Kk) {
        float s8 = 0.f;
#pragma unroll
        for (int w = 0; w < 8; w++) s8 += red2[t][w];
        g_part[(b * Kk + t) * NCH + chunk] = s8;
    }
    // phase 2: U_partial[s][d=t] = Σ_n as[s][n]·x̂[n][d]   (chunk is L2/L1-hot)
    float acc[Kk];
#pragma unroll
    for (int s = 0; s < Kk; s++) acc[s] = 0.f;
    const float* xp = xln + nbase * Dd + t;
#pragma unroll 2
    for (int n4 = 0; n4 < 64; n4++) {
        float x0 = xp[(4 * n4 + 0) * Dd];
        float x1 = xp[(4 * n4 + 1) * Dd];
        float x2 = xp[(4 * n4 + 2) * Dd];
        float x3 = xp[(4 * n4 + 3) * Dd];
#pragma unroll
        for (int s = 0; s < Kk; s++) {
            float4 a4 = *(const float4*)&as[s][4 * n4];
            acc[s] += a4.x * x0 + a4.y * x1 + a4.z * x2 + a4.w * x3;
        }
    }
#pragma unroll
    for (int s = 0; s < Kk; s++)
        g_updpart[((size_t)chunk * BK_TOT + b * Kk + s) * Dd + t] = acc[s];
}

// ---------------- fused slot update: U-reduce → GRU → MLP → LN → q ----------------
// grid 120, block 256, 8 slot-rows per block. Thread t owns output column t of
// each product; weight rows streamed as float4 (natural [out][in] layout).
__global__ __launch_bounds__(256) void slot_update_kernel(
    const float* __restrict__ whh, const float* __restrict__ w1,
    const float* __restrict__ w2,
    const float* __restrict__ bih, const float* __restrict__ bhh,
    const float* __restrict__ b1, const float* __restrict__ b2,
    const float* __restrict__ lnm_w, const float* __restrict__ lnm_b,
    const float* __restrict__ lns_w, const float* __restrict__ lns_b) {
    __shared__ float u_s[8][256];
    __shared__ float h_s[8][256];
    __shared__ float a_s[8][256];
    __shared__ float h1_s[8][512];
    __shared__ float inv_s[8];
    int t = threadIdx.x, lane = t & 31, wid = t >> 5;
    int row0 = blockIdx.x * 8;

#pragma unroll
    for (int r = 0; r < 8; r++) h_s[r][t] = g_slots[(size_t)(row0 + r) * Dd + t];
    if (t < 8) {
        float s = 0.f;
#pragma unroll
        for (int c = 0; c < NCH; c++) s += g_part[(row0 + t) * NCH + c];
        inv_s[t] = 1.0f / (s + 1e-8f);
    }
    __syncthreads();
#pragma unroll
    for (int r = 0; r < 8; r++) {
        float a = 0.f;
#pragma unroll
        for (int c = 0; c < NCH; c++)
            a += g_updpart[((size_t)c * BK_TOT + row0 + r) * Dd + t];
        u_s[r][t] = a * inv_s[r];
    }
    __syncthreads();

    // GRU gates: thread t computes gate columns t (r), 256+t (z), 512+t (n)
    float ri[8] = {0}, rh[8] = {0}, zi[8] = {0}, zh[8] = {0}, ni[8] = {0}, nh[8] = {0};
    dot4<64>(ri, &u_s[0][0], 256, g_wiv + (size_t)t * Dd);
    dot4<64>(zi, &u_s[0][0], 256, g_wiv + (size_t)(256 + t) * Dd);
    dot4<64>(ni, &u_s[0][0], 256, g_wiv + (size_t)(512 + t) * Dd);
    dot4<64>(rh, &h_s[0][0], 256, whh + (size_t)t * Dd);
    dot4<64>(zh, &h_s[0][0], 256, whh + (size_t)(256 + t) * Dd);
    dot4<64>(nh, &h_s[0][0], 256, whh + (size_t)(512 + t) * Dd);
    float bir = bih[t], bhr = bhh[t];
    float biz = bih[256 + t], bhz = bhh[256 + t];
    float bin = bih[512 + t], bhn = bhh[512 + t];
    __syncthreads();
#pragma unroll
    for (int r = 0; r < 8; r++) {
        float rg = sigmoidf_(ri[r] + bir + rh[r] + bhr);
        float zg = sigmoidf_(zi[r] + biz + zh[r] + bhz);
        float ng = tanhf(ni[r] + bin + rg * (nh[r] + bhn));
        h_s[r][t] = (1.0f - zg) * ng + zg * h_s[r][t];
    }
    __syncthreads();
    // ln_mlp
    warp_ln_row(&h_s[wid][0], &a_s[wid][0], lnm_w, lnm_b, lane);
    __syncthreads();
    // mlp1 (relu): thread t computes h1 columns t and 256+t
    float m0[8] = {0}, m1[8] = {0};
    dot4<64>(m0, &a_s[0][0], 256, w1 + (size_t)t * Dd);
    dot4<64>(m1, &a_s[0][0], 256, w1 + (size_t)(256 + t) * Dd);
    float b1a = b1[t], b1b = b1[256 + t];
#pragma unroll
    for (int r = 0; r < 8; r++) {
        h1_s[r][t] = fmaxf(m0[r] + b1a, 0.f);
        h1_s[r][256 + t] = fmaxf(m1[r] + b1b, 0.f);
    }
    __syncthreads();
    // mlp2 + residual
    float m2[8] = {0};
    dot4<128>(m2, &h1_s[0][0], 512, w2 + (size_t)t * Hh);
    float b2t = b2[t];
#pragma unroll
    for (int r = 0; r < 8; r++) {
        float ns = h_s[r][t] + m2[r] + b2t;
        g_slots[(size_t)(row0 + r) * Dd + t] = ns;
        a_s[r][t] = ns;
    }
    __syncthreads();
    // ln_slots → u_s, then q for next iteration / final attention
    warp_ln_row(&a_s[wid][0], &u_s[wid][0], lns_w, lns_b, lane);
    __syncthreads();
    float qa[8] = {0};
    dot4<64>(qa, &u_s[0][0], 256, g_wqk + (size_t)t * Dd);
#pragma unroll
    for (int r = 0; r < 8; r++) g_q[(size_t)(row0 + r) * Dd + t] = qa[r];
}

__global__ void copy_kernel(const float* __restrict__ src, float* __restrict__ dst, int n) {
    int i = blockIdx.x * 256 + threadIdx.x;
    if (i < n) dst[i] = src[i];
}

// ---------------- host orchestration ----------------
extern "C" void kernel_launch(void* const* d_in, const int* in_sizes, int n_in,
                              void* d_out, int out_size) {
    const float* inputs        = (const float*)d_in[0];
    const float* slot_noise    = (const float*)d_in[1];
    const float* slots_mu      = (const float*)d_in[2];
    const float* slots_logsig  = (const float*)d_in[3];
    const float* Wq            = (const float*)d_in[4];
    const float* Wk            = (const float*)d_in[5];
    const float* Wv            = (const float*)d_in[6];
    const float* w_ih          = (const float*)d_in[7];
    const float* w_hh          = (const float*)d_in[8];
    const float* b_ih          = (const float*)d_in[9];
    const float* b_hh          = (const float*)d_in[10];
    const float* mlp_w1        = (const float*)d_in[11];
    const float* mlp_b1        = (const float*)d_in[12];
    const float* mlp_w2        = (const float*)d_in[13];
    const float* mlp_b2        = (const float*)d_in[14];
    const float* ln_in_w       = (const float*)d_in[15];
    const float* ln_in_b       = (const float*)d_in[16];
    const float* ln_s_w        = (const float*)d_in[17];
    const float* ln_s_b        = (const float*)d_in[18];
    const float* ln_m_w        = (const float*)d_in[19];
    const float* ln_m_b        = (const float*)d_in[20];
    float* out = (float*)d_out;

    float *p_xln, *p_wqk, *p_wiv, *p_q, *p_slots;
    cudaGetSymbolAddress((void**)&p_xln, g_xln);
    cudaGetSymbolAddress((void**)&p_wqk, g_wqk);
    cudaGetSymbolAddress((void**)&p_wiv, g_wiv);
    cudaGetSymbolAddress((void**)&p_q, g_q);
    cudaGetSymbolAddress((void**)&p_slots, g_slots);

    // setup: x̂, folded weights (natural layouts), slots, initial q
    ln_apply_kernel<<<BN_TOT / 8, dim3(32, 8)>>>(inputs, p_xln, ln_in_w, ln_in_b);
    atb_kernel<<<dim3(4, 4), 256>>>(Wk, Wq, p_wqk);      // wqk[e][d]
    ab_kernel<<<dim3(12, 4), 256>>>(w_ih, Wv, p_wiv);    // wiv[g][e]
    slots_init_kernel<<<BK_TOT, 256>>>(slots_mu, slots_logsig, slot_noise);
    slot_lnq_kernel<<<120, 256>>>(ln_s_w, ln_s_b);

    for (int it = 0; it < 3; it++) {
        attn_pass_kernel<<<dim3(NCH, Bb), 256>>>(p_q, p_xln, nullptr, 0);
        slot_update_kernel<<<120, 256>>>(w_hh, mlp_w1, mlp_w2, b_ih, b_hh,
                                         mlp_b1, mlp_b2, ln_m_w, ln_m_b, ln_s_w, ln_s_b);
    }

    // final attention (softmax only) + slots output
    attn_pass_kernel<<<dim3(NCH, Bb), 256>>>(p_q, p_xln, out + BK_TOT * Dd, 1);
    copy_kernel<<<960, 256>>>(p_slots, out, BK_TOT * Dd);
}